// round 4
// baseline (speedup 1.0000x reference)
#include <cuda_runtime.h>
#include <math.h>

#define BB 64
#define TT 101
#define TS 100
#define VV 8000
#define HH 512
#define GG 2048
#define MM (TS*BB)   // 6400
#define EPSN 1e-5f

typedef unsigned long long ull;

// ---------------- device scratch (static; no runtime allocation) -------------
__device__ float g_e[MM*HH];                     // [m][h] embedded inputs, m = t*64+b
__device__ float g_Xg1[(size_t)GG*MM];           // [t][n][b] precomputed e@Wih1^T + b1
__device__ float g_Hout[MM*HH];                  // [m][h] layer-3 bn*mask output per step
__device__ float g_logits[(size_t)MM*VV];        // [m][v]
__device__ float g_part2[16*GG*BB];              // [slice][n][b] split-K partials
__device__ float g_h[3*HH*BB];                   // [layer][j][b]
__device__ float g_c[3*HH*BB];                   // [layer][j][b]
__device__ float g_hd[2*HH*BB];                  // [layer][j][b]
__device__ unsigned g_flags[128];                // distributed grid-barrier flags

// ---------------- f32x2 helpers ----------------------------------------------
__device__ __forceinline__ ull fma2(ull a, ull b, ull c) {
    ull d;
    asm("fma.rn.f32x2 %0, %1, %2, %3;" : "=l"(d) : "l"(a), "l"(b), "l"(c));
    return d;
}
__device__ __forceinline__ ull pack2(float x, float y) {
    ull r;
    asm("mov.b64 %0, {%1, %2};" : "=l"(r) : "f"(x), "f"(y));
    return r;
}
__device__ __forceinline__ ull dup2(float x) {
    ull r;
    asm("mov.b64 %0, {%1, %1};" : "=l"(r) : "f"(x));
    return r;
}
__device__ __forceinline__ float2 unpack2(ull v) {
    float2 r;
    asm("mov.b64 {%0, %1}, %2;" : "=f"(r.x), "=f"(r.y) : "l"(v));
    return r;
}

// ---------------- distributed grid barrier (128 co-resident CTAs) ------------
__device__ __forceinline__ void gridbar(unsigned epoch) {
    __syncthreads();
    if (threadIdx.x == 0)
        asm volatile("st.release.gpu.u32 [%0], %1;"
                     :: "l"(&g_flags[blockIdx.x]), "r"(epoch) : "memory");
    if (threadIdx.x < 128) {
        unsigned v;
        do {
            asm volatile("ld.acquire.gpu.u32 %0, [%1];"
                         : "=r"(v) : "l"(&g_flags[threadIdx.x]) : "memory");
        } while (v < epoch);
    }
    __syncthreads();
}

// ---------------- init: zero states + flags + loss slot ----------------------
__global__ void k_init(float* out, int hasLoss) {
    int i = blockIdx.x * blockDim.x + threadIdx.x;
    if (i < 3*HH*BB) { g_h[i] = 0.f; g_c[i] = 0.f; }
    if (i < 128) g_flags[i] = 0u;
    if (i == 0 && hasLoss) out[0] = 0.f;
}

// ---------------- embedding gather -------------------------------------------
__global__ void k_embed(const int* x, const float* emb) {
    int i = blockIdx.x * blockDim.x + threadIdx.x;
    if (i >= MM * (HH/4)) return;
    int m  = i / (HH/4);
    int hq = i % (HH/4);
    int t = m / BB, b = m % BB;
    int tok = x[b*TT + t];
    ((float4*)g_e)[(size_t)m*(HH/4) + hq] =
        ((const float4*)emb)[(size_t)tok*(HH/4) + hq];
}

// ---------------- big SGEMM (f32x2): 128x128 tile, pairs along m -------------
// MODE 0: g_Xg1[t][n][b] = g_e @ Wih1^T + b1, N=2048
// MODE 1: g_logits[m][v] = g_Hout @ Wd^T + bd, N=8000
template<int MODE>
__global__ void __launch_bounds__(256) k_gemm_big(const float* __restrict__ Bw,
                                                  const float* __restrict__ bias) {
    const int N = (MODE == 0) ? GG : VV;
    const float* A = (MODE == 0) ? g_e : g_Hout;
    __shared__ __align__(16) float Ast[16][132];
    __shared__ __align__(16) ull   Bst2[16][132];
    int tid = threadIdx.x;
    int mBase = blockIdx.y * 128, nBase = blockIdx.x * 128;
    int lr = tid >> 2, lc = (tid & 3) * 4;
    int m0 = (tid >> 4) * 8, n0 = (tid & 15) * 8;
    ull acc[4][8];
#pragma unroll
    for (int i = 0; i < 4; i++)
#pragma unroll
        for (int j = 0; j < 8; j++) acc[i][j] = 0ull;

    for (int kb = 0; kb < 512; kb += 16) {
        float4 av0 = *(const float4*)&A[(size_t)(mBase + lr)*512 + kb + lc];
        float4 av1 = *(const float4*)&A[(size_t)(mBase + lr + 64)*512 + kb + lc];
        int ng0 = nBase + lr, ng1 = nBase + lr + 64;
        float4 bv0 = make_float4(0.f,0.f,0.f,0.f), bv1 = make_float4(0.f,0.f,0.f,0.f);
        if (ng0 < N) bv0 = *(const float4*)&Bw[(size_t)ng0*512 + kb + lc];
        if (ng1 < N) bv1 = *(const float4*)&Bw[(size_t)ng1*512 + kb + lc];
        __syncthreads();
        Ast[lc+0][lr] = av0.x; Ast[lc+1][lr] = av0.y; Ast[lc+2][lr] = av0.z; Ast[lc+3][lr] = av0.w;
        Ast[lc+0][lr+64] = av1.x; Ast[lc+1][lr+64] = av1.y; Ast[lc+2][lr+64] = av1.z; Ast[lc+3][lr+64] = av1.w;
        Bst2[lc+0][lr] = pack2(bv0.x, bv0.x); Bst2[lc+1][lr] = pack2(bv0.y, bv0.y);
        Bst2[lc+2][lr] = pack2(bv0.z, bv0.z); Bst2[lc+3][lr] = pack2(bv0.w, bv0.w);
        Bst2[lc+0][lr+64] = pack2(bv1.x, bv1.x); Bst2[lc+1][lr+64] = pack2(bv1.y, bv1.y);
        Bst2[lc+2][lr+64] = pack2(bv1.z, bv1.z); Bst2[lc+3][lr+64] = pack2(bv1.w, bv1.w);
        __syncthreads();
#pragma unroll
        for (int kk = 0; kk < 16; kk++) {
            ull a2[4], w2[8];
#pragma unroll
            for (int i = 0; i < 4; i++) a2[i] = *(const ull*)&Ast[kk][m0 + 2*i];
#pragma unroll
            for (int j = 0; j < 8; j++) w2[j] = Bst2[kk][n0 + j];
#pragma unroll
            for (int i = 0; i < 4; i++)
#pragma unroll
                for (int j = 0; j < 8; j++) acc[i][j] = fma2(a2[i], w2[j], acc[i][j]);
        }
    }

    if (MODE == 0) {
#pragma unroll
        for (int j = 0; j < 8; j++) {
            int n = nBase + n0 + j;
            float bb = bias[n];
#pragma unroll
            for (int i = 0; i < 4; i++) {
                int m = mBase + m0 + 2*i;
                float2 v = unpack2(acc[i][j]);
                v.x += bb; v.y += bb;
                int tt = m >> 6, bc = m & 63;   // pair stays inside one t-group
                *(float2*)&g_Xg1[(size_t)tt*(GG*BB) + (size_t)n*BB + bc] = v;
            }
        }
    } else {
#pragma unroll
        for (int i = 0; i < 4; i++) {
            int m = mBase + m0 + 2*i;
#pragma unroll
            for (int j = 0; j < 8; j++) {
                int n = nBase + n0 + j;
                if (n < VV) {
                    float2 v = unpack2(acc[i][j]);
                    float bb = bias[n];
                    g_logits[(size_t)m*VV + n]     = v.x + bb;
                    g_logits[(size_t)(m+1)*VV + n] = v.y + bb;
                }
            }
        }
    }
}

// ---------------- GEMM slice body (weights resident in smem) -----------------
// acc pairs along b. A in smem [k][64] natural floats. W in smem [k][256] floats.
template<int KLEN>
__device__ __forceinline__ void gemm_slice(const float* __restrict__ As,
                                           const float* __restrict__ Wsm,
                                           int b0, int n0, float* __restrict__ P) {
    ull acc[4][8];
#pragma unroll
    for (int i = 0; i < 4; i++)
#pragma unroll
        for (int j = 0; j < 8; j++) acc[i][j] = 0ull;

#pragma unroll 4
    for (int k = 0; k < KLEN; k++) {
        ull a2[4];
        const ull* ap = (const ull*)&As[k*64 + b0];
#pragma unroll
        for (int i = 0; i < 4; i++) a2[i] = ap[i];
        float4 wlo = *(const float4*)&Wsm[k*256 + n0];
        float4 whi = *(const float4*)&Wsm[k*256 + n0 + 4];
        ull w2[8];
        w2[0] = dup2(wlo.x); w2[1] = dup2(wlo.y); w2[2] = dup2(wlo.z); w2[3] = dup2(wlo.w);
        w2[4] = dup2(whi.x); w2[5] = dup2(whi.y); w2[6] = dup2(whi.z); w2[7] = dup2(whi.w);
#pragma unroll
        for (int i = 0; i < 4; i++)
#pragma unroll
            for (int j = 0; j < 8; j++) acc[i][j] = fma2(a2[i], w2[j], acc[i][j]);
    }
    // write partials [n][b] as 16B stores
#pragma unroll
    for (int j = 0; j < 8; j++) {
#pragma unroll
        for (int ii = 0; ii < 2; ii++) {
            ulonglong2 v; v.x = acc[2*ii][j]; v.y = acc[2*ii+1][j];
            *(ulonglong2*)&P[(size_t)(n0 + j)*BB + b0 + 4*ii] = v;
        }
    }
}

// ---------------- persistent recurrence kernel -------------------------------
// 128 CTAs x 256 threads, 1 CTA/SM (176KB dynamic smem).
// Weights loaded into smem ONCE, resident for all 100 steps.
__global__ void __launch_bounds__(256, 1) k_persist(
    const float* __restrict__ Whh1,
    const float* __restrict__ Wih2, const float* __restrict__ Whh2,
    const float* __restrict__ Wih3, const float* __restrict__ Whh3,
    const float* __restrict__ b2,   const float* __restrict__ b3,
    const float* __restrict__ gm0, const float* __restrict__ bt0, const float* __restrict__ mk0,
    const float* __restrict__ gm1, const float* __restrict__ bt1, const float* __restrict__ mk1,
    const float* __restrict__ gm2, const float* __restrict__ bt2, const float* __restrict__ mk2)
{
    extern __shared__ __align__(16) float sm[];
    float* W0s = sm;                 // [32][256]
    float* W1s = sm + 32*256;        // [64][256]
    float* W2s = sm + 96*256;        // [64][256]
    float* As  = sm + 160*256;       // [64][64]
    __shared__ float sS[4][2], sQ[4][2];

    int tid = threadIdx.x;
    int ntile = blockIdx.x >> 4;         // 0..7 -> 256 n each
    int slice = blockIdx.x & 15;         // 0..15 K-slices
    int nb = ntile << 8;
    int b0 = (tid & 7) * 8;              // 8 b per thread
    int n0 = (tid >> 3) * 8;             // 8 n per thread (n0 in 0..248)
    int jloc = tid >> 6, bcell = tid & 63;
    int jglob = (blockIdx.x << 2) + jloc;

    // -------- one-time weight load: Wsm[k][n] transposed-in-smem --------
    {
        const float* s0 = Whh1 + (size_t)(nb + tid)*HH + slice*32;
#pragma unroll
        for (int k = 0; k < 32; k += 4) {
            float4 w = *(const float4*)&s0[k];
            W0s[(k+0)*256 + tid] = w.x; W0s[(k+1)*256 + tid] = w.y;
            W0s[(k+2)*256 + tid] = w.z; W0s[(k+3)*256 + tid] = w.w;
        }
        const float* m1 = (slice < 8) ? Wih2 : Whh2;
        const float* s1 = m1 + (size_t)(nb + tid)*HH + (slice & 7)*64;
#pragma unroll
        for (int k = 0; k < 64; k += 4) {
            float4 w = *(const float4*)&s1[k];
            W1s[(k+0)*256 + tid] = w.x; W1s[(k+1)*256 + tid] = w.y;
            W1s[(k+2)*256 + tid] = w.z; W1s[(k+3)*256 + tid] = w.w;
        }
        const float* m2 = (slice < 8) ? Wih3 : Whh3;
        const float* s2 = m2 + (size_t)(nb + tid)*HH + (slice & 7)*64;
#pragma unroll
        for (int k = 0; k < 64; k += 4) {
            float4 w = *(const float4*)&s2[k];
            W2s[(k+0)*256 + tid] = w.x; W2s[(k+1)*256 + tid] = w.y;
            W2s[(k+2)*256 + tid] = w.z; W2s[(k+3)*256 + tid] = w.w;
        }
    }
    __syncthreads();

    float* Pout = g_part2 + ((size_t)slice*GG + nb)*BB;
    unsigned nbar = 0;

    for (int t = 0; t < TS; t++) {
#pragma unroll 1
        for (int l = 0; l < 3; l++) {
            // ================= GEMM phase =================
            const float* Aglob;
            if (l == 0)          Aglob = g_h + slice*32*BB;
            else if (slice < 8)  Aglob = g_hd + (l-1)*HH*BB + slice*64*BB;
            else                 Aglob = g_h  + l*HH*BB + (slice-8)*64*BB;
            int klen = (l == 0) ? 32 : 64;
            // stage A slice [klen][64] (cross-CTA data -> L2 load)
            for (int idx = tid; idx < klen*16; idx += 256) {
                int k = idx >> 4, c = (idx & 15) << 2;
                float4 v = __ldcg((const float4*)&Aglob[(size_t)k*BB + c]);
                *(float4*)&As[k*64 + c] = v;
            }
            __syncthreads();

            if (l == 0)      gemm_slice<32>(As, W0s, b0, n0, Pout);
            else if (l == 1) gemm_slice<64>(As, W1s, b0, n0, Pout);
            else             gemm_slice<64>(As, W2s, b0, n0, Pout);

            nbar++; gridbar(nbar);

            // ================= CELL + BN + dropout phase =================
            {
                const float* biasP = (l == 1) ? b2 : b3;
                const float* gmP = (l == 0) ? gm0 : (l == 1) ? gm1 : gm2;
                const float* btP = (l == 0) ? bt0 : (l == 1) ? bt1 : bt2;
                const float* mkP = (l == 0) ? mk0 : (l == 1) ? mk1 : mk2;
                float gate[4];
#pragma unroll
                for (int g = 0; g < 4; g++) {
                    int n = (g << 9) + jglob;
                    float s = (l == 0)
                        ? g_Xg1[(size_t)t*(GG*BB) + (size_t)n*BB + bcell]
                        : biasP[n];
                    const float* pp = g_part2 + (size_t)n*BB + bcell;
#pragma unroll
                    for (int sl = 0; sl < 16; sl++)
                        s += __ldcg(pp + (size_t)sl*(GG*BB));
                    gate[g] = s;
                }
                float* hP = g_h + l*HH*BB;
                float* cP = g_c + l*HH*BB;
                float iv = 1.f / (1.f + __expf(-gate[0]));
                float fv = 1.f / (1.f + __expf(-gate[1]));
                float gv = tanhf(gate[2]);
                float ov = 1.f / (1.f + __expf(-gate[3]));
                float cc = fv * cP[jglob*BB + bcell] + iv * gv;
                float hh = ov * tanhf(cc);
                cP[jglob*BB + bcell] = cc;
                hP[jglob*BB + bcell] = hh;

                // BN over batch (64 threads = 2 warps per feature j)
                float sum = hh, sq = hh * hh;
#pragma unroll
                for (int o = 16; o; o >>= 1) {
                    sum += __shfl_down_sync(0xffffffffu, sum, o);
                    sq  += __shfl_down_sync(0xffffffffu, sq,  o);
                }
                int w = (tid >> 5) & 1;
                if ((tid & 31) == 0) { sS[jloc][w] = sum; sQ[jloc][w] = sq; }
                __syncthreads();
                float mu  = (sS[jloc][0] + sS[jloc][1]) * (1.f / BB);
                float var = (sQ[jloc][0] + sQ[jloc][1]) * (1.f / BB) - mu * mu;
                float hd = (gmP[jglob] * (hh - mu) * rsqrtf(var + EPSN) + btP[jglob])
                           * mkP[bcell*HH + jglob];
                if (l < 2) g_hd[l*HH*BB + jglob*BB + bcell] = hd;
                else       g_Hout[((size_t)t*BB + bcell)*HH + jglob] = hd;
            }
            nbar++; gridbar(nbar);
        }
    }
}

// ---------------- loss: mean NLL over 6400 rows of 8000 logits --------------
__global__ void k_loss(const int* __restrict__ x, float* out) {
    int r = blockIdx.x;            // r = t*64 + b
    int t = r >> 6, b = r & 63;
    const float* row = &g_logits[(size_t)r * VV];
    int tid = threadIdx.x;
    float m = -INFINITY, s = 0.f;
    for (int v = tid; v < VV; v += 256) {
        float xv = row[v];
        if (xv > m) { s = s * expf(m - xv) + 1.f; m = xv; }
        else s += expf(xv - m);
    }
    __shared__ float sm[256], ss[256];
    sm[tid] = m; ss[tid] = s;
    __syncthreads();
    for (int o = 128; o; o >>= 1) {
        if (tid < o) {
            float m2 = sm[tid + o], s2 = ss[tid + o];
            float mm = fmaxf(sm[tid], m2);
            ss[tid] = ss[tid] * expf(sm[tid] - mm) + s2 * expf(m2 - mm);
            sm[tid] = mm;
        }
        __syncthreads();
    }
    if (tid == 0) {
        int tgt = x[b*TT + t + 1];
        float lse = sm[0] + logf(ss[0]);
        atomicAdd(out, (lse - row[tgt]) * (1.f / MM));
    }
}

// ---------------- transpose [t*64+b][v] -> out[b][v][t] ---------------------
__global__ void k_transpose(float* __restrict__ outLogits) {
    int b = blockIdx.x;
    int v0 = blockIdx.y * 32;
    __shared__ float tile[32 * 101];
    int tid = threadIdx.x;
    for (int idx = tid; idx < 3200; idx += 256) {
        int t = idx >> 5, vi = idx & 31;
        tile[vi*101 + t] = g_logits[(size_t)(t*BB + b)*VV + v0 + vi];
    }
    __syncthreads();
    for (int idx = tid; idx < 3200; idx += 256) {
        int vi = idx / 100, t = idx - vi*100;
        outLogits[(size_t)b*VV*TS + (size_t)(v0 + vi)*TS + t] = tile[vi*101 + t];
    }
}

// ---------------- launch ------------------------------------------------------
extern "C" void kernel_launch(void* const* d_in, const int* in_sizes, int n_in,
                              void* d_out, int out_size) {
    const int*   x   = (const int*)d_in[0];
    const float* emb = (const float*)d_in[1];
    const float* Wd  = (const float*)d_in[2];
    const float* bd  = (const float*)d_in[3];
    const float* Wih[3] = {(const float*)d_in[4],  (const float*)d_in[10], (const float*)d_in[16]};
    const float* Whh[3] = {(const float*)d_in[5],  (const float*)d_in[11], (const float*)d_in[17]};
    const float* bl[3]  = {(const float*)d_in[6],  (const float*)d_in[12], (const float*)d_in[18]};
    const float* gm[3]  = {(const float*)d_in[7],  (const float*)d_in[13], (const float*)d_in[19]};
    const float* bt[3]  = {(const float*)d_in[8],  (const float*)d_in[14], (const float*)d_in[20]};
    const float* mk[3]  = {(const float*)d_in[9],  (const float*)d_in[15], (const float*)d_in[21]};

    float* out = (float*)d_out;
    int hasLoss = (out_size & 1) ? 1 : 0;   // 51,200,001 odd => loss + logits
    float* outLogits = out + hasLoss;

    const int PERSIST_SMEM = (160*256 + 64*64) * 4;   // 160KB W + 16KB A = 176KB
    static int attrDone = 0;
    if (!attrDone) {
        cudaFuncSetAttribute(k_persist, cudaFuncAttributeMaxDynamicSharedMemorySize,
                             PERSIST_SMEM);
        attrDone = 1;
    }

    k_init<<<(3*HH*BB + 255)/256, 256>>>(out, hasLoss);
    k_embed<<<(MM*(HH/4) + 255)/256, 256>>>(x, emb);
    k_gemm_big<0><<<dim3(GG/128, MM/128), 256>>>(Wih[0], bl[0]);

    k_persist<<<128, 256, PERSIST_SMEM>>>(
        Whh[0], Wih[1], Whh[1], Wih[2], Whh[2],
        bl[1], bl[2],
        gm[0], bt[0], mk[0],
        gm[1], bt[1], mk[1],
        gm[2], bt[2], mk[2]);

    k_gemm_big<1><<<dim3((VV + 127)/128, MM/128), 256>>>(Wd, bd);
    if (hasLoss) k_loss<<<MM, 256>>>(x, out);
    k_transpose<<<dim3(BB, VV/32), 256>>>(outLogits);
}

// round 5
// speedup vs baseline: 1.2936x; 1.2936x over previous
#include <cuda_runtime.h>
#include <math.h>

#define BB 64
#define TT 101
#define TS 100
#define VV 8000
#define HH 512
#define GG 2048
#define MM (TS*BB)   // 6400
#define EPSN 1e-5f

typedef unsigned long long ull;

// ---------------- device scratch (static; no runtime allocation) -------------
__device__ float g_e[MM*HH];                     // [m][h] embedded inputs, m = t*64+b
__device__ float g_Xg1[(size_t)GG*MM];           // [t][n][b] precomputed e@Wih1^T + b1
__device__ float g_Hout[MM*HH];                  // [m][h] layer-3 bn*mask output per step
__device__ float g_logits[(size_t)MM*VV];        // [m][v]
__device__ float g_part3[3*16*GG*BB];            // [layer][slice][n][b] split-K partials
__device__ float g_h[3*HH*BB];                   // [layer][j][b]
__device__ float g_c[3*HH*BB];                   // [layer][j][b]
__device__ float g_hd[2*HH*BB];                  // [layer][j][b]

// ---------------- f32x2 helpers ----------------------------------------------
__device__ __forceinline__ ull fma2(ull a, ull b, ull c) {
    ull d;
    asm("fma.rn.f32x2 %0, %1, %2, %3;" : "=l"(d) : "l"(a), "l"(b), "l"(c));
    return d;
}
__device__ __forceinline__ ull pack2(float x, float y) {
    ull r;
    asm("mov.b64 %0, {%1, %2};" : "=l"(r) : "f"(x), "f"(y));
    return r;
}
__device__ __forceinline__ ull dup2(float x) {
    ull r;
    asm("mov.b64 %0, {%1, %1};" : "=l"(r) : "f"(x));
    return r;
}
__device__ __forceinline__ float2 unpack2(ull v) {
    float2 r;
    asm("mov.b64 {%0, %1}, %2;" : "=f"(r.x), "=f"(r.y) : "l"(v));
    return r;
}

// ---------------- init: zero states + loss slot ------------------------------
__global__ void k_init(float* out, int hasLoss) {
    int i = blockIdx.x * blockDim.x + threadIdx.x;
    if (i < 3*HH*BB) { g_h[i] = 0.f; g_c[i] = 0.f; }
    if (i == 0 && hasLoss) out[0] = 0.f;
}

// ---------------- embedding gather -------------------------------------------
__global__ void k_embed(const int* x, const float* emb) {
    int i = blockIdx.x * blockDim.x + threadIdx.x;
    if (i >= MM * (HH/4)) return;
    int m  = i / (HH/4);
    int hq = i % (HH/4);
    int t = m / BB, b = m % BB;
    int tok = x[b*TT + t];
    ((float4*)g_e)[(size_t)m*(HH/4) + hq] =
        ((const float4*)emb)[(size_t)tok*(HH/4) + hq];
}

// ---------------- big SGEMM (f32x2): 128x128 tile, pairs along m -------------
// MODE 0: g_Xg1[t][n][b] = g_e @ Wih1^T + b1, N=2048
// MODE 1: g_logits[m][v] = g_Hout @ Wd^T + bd, N=8000
template<int MODE>
__global__ void __launch_bounds__(256) k_gemm_big(const float* __restrict__ Bw,
                                                  const float* __restrict__ bias) {
    const int N = (MODE == 0) ? GG : VV;
    const float* A = (MODE == 0) ? g_e : g_Hout;
    __shared__ __align__(16) float Ast[16][132];
    __shared__ __align__(16) ull   Bst2[16][132];
    int tid = threadIdx.x;
    int mBase = blockIdx.y * 128, nBase = blockIdx.x * 128;
    int lr = tid >> 2, lc = (tid & 3) * 4;
    int m0 = (tid >> 4) * 8, n0 = (tid & 15) * 8;
    ull acc[4][8];
#pragma unroll
    for (int i = 0; i < 4; i++)
#pragma unroll
        for (int j = 0; j < 8; j++) acc[i][j] = 0ull;

    for (int kb = 0; kb < 512; kb += 16) {
        float4 av0 = *(const float4*)&A[(size_t)(mBase + lr)*512 + kb + lc];
        float4 av1 = *(const float4*)&A[(size_t)(mBase + lr + 64)*512 + kb + lc];
        int ng0 = nBase + lr, ng1 = nBase + lr + 64;
        float4 bv0 = make_float4(0.f,0.f,0.f,0.f), bv1 = make_float4(0.f,0.f,0.f,0.f);
        if (ng0 < N) bv0 = *(const float4*)&Bw[(size_t)ng0*512 + kb + lc];
        if (ng1 < N) bv1 = *(const float4*)&Bw[(size_t)ng1*512 + kb + lc];
        __syncthreads();
        Ast[lc+0][lr] = av0.x; Ast[lc+1][lr] = av0.y; Ast[lc+2][lr] = av0.z; Ast[lc+3][lr] = av0.w;
        Ast[lc+0][lr+64] = av1.x; Ast[lc+1][lr+64] = av1.y; Ast[lc+2][lr+64] = av1.z; Ast[lc+3][lr+64] = av1.w;
        Bst2[lc+0][lr] = pack2(bv0.x, bv0.x); Bst2[lc+1][lr] = pack2(bv0.y, bv0.y);
        Bst2[lc+2][lr] = pack2(bv0.z, bv0.z); Bst2[lc+3][lr] = pack2(bv0.w, bv0.w);
        Bst2[lc+0][lr+64] = pack2(bv1.x, bv1.x); Bst2[lc+1][lr+64] = pack2(bv1.y, bv1.y);
        Bst2[lc+2][lr+64] = pack2(bv1.z, bv1.z); Bst2[lc+3][lr+64] = pack2(bv1.w, bv1.w);
        __syncthreads();
#pragma unroll
        for (int kk = 0; kk < 16; kk++) {
            ull a2[4], w2[8];
#pragma unroll
            for (int i = 0; i < 4; i++) a2[i] = *(const ull*)&Ast[kk][m0 + 2*i];
#pragma unroll
            for (int j = 0; j < 8; j++) w2[j] = Bst2[kk][n0 + j];
#pragma unroll
            for (int i = 0; i < 4; i++)
#pragma unroll
                for (int j = 0; j < 8; j++) acc[i][j] = fma2(a2[i], w2[j], acc[i][j]);
        }
    }

    if (MODE == 0) {
#pragma unroll
        for (int j = 0; j < 8; j++) {
            int n = nBase + n0 + j;
            float bb = bias[n];
#pragma unroll
            for (int i = 0; i < 4; i++) {
                int m = mBase + m0 + 2*i;
                float2 v = unpack2(acc[i][j]);
                v.x += bb; v.y += bb;
                int tt = m >> 6, bc = m & 63;   // pair stays inside one t-group
                *(float2*)&g_Xg1[(size_t)tt*(GG*BB) + (size_t)n*BB + bc] = v;
            }
        }
    } else {
#pragma unroll
        for (int i = 0; i < 4; i++) {
            int m = mBase + m0 + 2*i;
#pragma unroll
            for (int j = 0; j < 8; j++) {
                int n = nBase + n0 + j;
                if (n < VV) {
                    float2 v = unpack2(acc[i][j]);
                    float bb = bias[n];
                    g_logits[(size_t)m*VV + n]     = v.x + bb;
                    g_logits[(size_t)(m+1)*VV + n] = v.y + bb;
                }
            }
        }
    }
}

// ---------------- wavefront GEMM: diagonal d = t + l --------------------------
// grid (32 n-tiles, 16 K-slices, 3 layers), block 256.
// Each CTA: 64n x 64b x 64k slice -> partials g_part3[l][slice][n][b].
// Layer 0: K=512 (Whh1 only; Wih1 precomputed in Xg1) -> slices 0..7.
// Layers 1,2: K=1024: slices 0..7 = Wih @ hd(l-1), 8..15 = Whh @ h(l).
__global__ void __launch_bounds__(256) k_gemm_wave(int d,
    const float* __restrict__ Whh1,
    const float* __restrict__ Wih2, const float* __restrict__ Whh2,
    const float* __restrict__ Wih3, const float* __restrict__ Whh3)
{
    int l = blockIdx.z;
    int t = d - l;
    if (t < 0 || t >= TS) return;
    int slice = blockIdx.y;
    if (l == 0 && slice >= 8) return;

    const float* A; const float* W;
    if (l == 0) {
        A = g_h + slice*64*BB;
        W = Whh1 + slice*64;
    } else if (slice < 8) {
        A = g_hd + (l-1)*HH*BB + slice*64*BB;
        W = ((l == 1) ? Wih2 : Wih3) + slice*64;
    } else {
        A = g_h + l*HH*BB + (slice-8)*64*BB;
        W = ((l == 1) ? Whh2 : Whh3) + (slice-8)*64;
    }
    int nb = blockIdx.x * 64;
    int tid = threadIdx.x;

    __shared__ __align__(16) float Ast[64*64];   // [k][b] 16KB
    __shared__ __align__(16) ull   Wst[64*64];   // [k][n] dup pairs 32KB

    // stage A slice [64k][64b]
    for (int idx = tid; idx < 64*16; idx += 256) {
        int k = idx >> 4, c = (idx & 15) * 4;
        *(float4*)&Ast[k*64 + c] = *(const float4*)&A[(size_t)k*BB + c];
    }
    // stage W slice as duplicated pairs [64k][64n]
    {
        int n = tid & 63, kq = tid >> 6;     // kq 0..3, 16 k each
        const float* wp = W + (size_t)(nb + n)*HH + kq*16;
#pragma unroll
        for (int c = 0; c < 16; c += 4) {
            float4 w = *(const float4*)&wp[c];
            int k = kq*16 + c;
            Wst[(k+0)*64 + n] = dup2(w.x);
            Wst[(k+1)*64 + n] = dup2(w.y);
            Wst[(k+2)*64 + n] = dup2(w.z);
            Wst[(k+3)*64 + n] = dup2(w.w);
        }
    }
    __syncthreads();

    int b0 = (tid & 15) * 4;     // 4 b (2 ull pairs)
    int n0 = (tid >> 4) * 4;     // 4 n
    ull acc[4][2];
#pragma unroll
    for (int j = 0; j < 4; j++) { acc[j][0] = 0ull; acc[j][1] = 0ull; }

#pragma unroll 8
    for (int k = 0; k < 64; k++) {
        ulonglong2 av  = *(const ulonglong2*)&Ast[k*64 + b0];
        ulonglong2 wv0 = *(const ulonglong2*)&Wst[k*64 + n0];
        ulonglong2 wv1 = *(const ulonglong2*)&Wst[k*64 + n0 + 2];
        acc[0][0] = fma2(av.x, wv0.x, acc[0][0]); acc[0][1] = fma2(av.y, wv0.x, acc[0][1]);
        acc[1][0] = fma2(av.x, wv0.y, acc[1][0]); acc[1][1] = fma2(av.y, wv0.y, acc[1][1]);
        acc[2][0] = fma2(av.x, wv1.x, acc[2][0]); acc[2][1] = fma2(av.y, wv1.x, acc[2][1]);
        acc[3][0] = fma2(av.x, wv1.y, acc[3][0]); acc[3][1] = fma2(av.y, wv1.y, acc[3][1]);
    }

    float* P = g_part3 + ((size_t)(l*16 + slice)*GG + nb)*BB;
#pragma unroll
    for (int j = 0; j < 4; j++) {
        ulonglong2 v; v.x = acc[j][0]; v.y = acc[j][1];
        *(ulonglong2*)&P[(size_t)(n0 + j)*BB + b0] = v;
    }
}

// ---------------- wavefront cell: LSTM + BN(train) + locked dropout ----------
// grid (512 j, 3 layers), block 64 (batch).
__global__ void k_cell_wave(int d,
    const float* __restrict__ b2, const float* __restrict__ b3,
    const float* __restrict__ gm0, const float* __restrict__ bt0, const float* __restrict__ mk0,
    const float* __restrict__ gm1, const float* __restrict__ bt1, const float* __restrict__ mk1,
    const float* __restrict__ gm2, const float* __restrict__ bt2, const float* __restrict__ mk2)
{
    int l = blockIdx.y;
    int t = d - l;
    if (t < 0 || t >= TS) return;
    int j = blockIdx.x;
    int b = threadIdx.x;
    int nsl = (l == 0) ? 8 : 16;
    const float* biasP = (l == 1) ? b2 : b3;
    const float* gmP = (l == 0) ? gm0 : (l == 1) ? gm1 : gm2;
    const float* btP = (l == 0) ? bt0 : (l == 1) ? bt1 : bt2;
    const float* mkP = (l == 0) ? mk0 : (l == 1) ? mk1 : mk2;

    float gate[4];
#pragma unroll
    for (int g = 0; g < 4; g++) {
        int n = (g << 9) + j;
        float s = (l == 0)
            ? g_Xg1[(size_t)t*(GG*BB) + (size_t)n*BB + b]
            : biasP[n];
        const float* pp = g_part3 + ((size_t)(l*16)*GG + n)*BB + b;
        for (int sl = 0; sl < nsl; sl++)
            s += pp[(size_t)sl*(GG*BB)];
        gate[g] = s;
    }
    float* hP = g_h + l*HH*BB;
    float* cP = g_c + l*HH*BB;
    float iv = 1.f / (1.f + expf(-gate[0]));
    float fv = 1.f / (1.f + expf(-gate[1]));
    float gv = tanhf(gate[2]);
    float ov = 1.f / (1.f + expf(-gate[3]));
    float cc = fv * cP[j*BB + b] + iv * gv;
    float hh = ov * tanhf(cc);
    cP[j*BB + b] = cc;
    hP[j*BB + b] = hh;

    // BatchNorm over batch (64 threads = 2 warps)
    float sum = hh, sq = hh * hh;
#pragma unroll
    for (int o = 16; o; o >>= 1) {
        sum += __shfl_down_sync(0xffffffffu, sum, o);
        sq  += __shfl_down_sync(0xffffffffu, sq,  o);
    }
    __shared__ float s0[2], s1[2];
    int warp = b >> 5, lane = b & 31;
    if (lane == 0) { s0[warp] = sum; s1[warp] = sq; }
    __syncthreads();
    float mu  = (s0[0] + s0[1]) * (1.f / BB);
    float var = (s1[0] + s1[1]) * (1.f / BB) - mu * mu;
    float hd = (gmP[j] * (hh - mu) * rsqrtf(var + EPSN) + btP[j]) * mkP[b*HH + j];
    if (l < 2) g_hd[l*HH*BB + j*BB + b] = hd;
    else       g_Hout[((size_t)t*BB + b)*HH + j] = hd;
}

// ---------------- loss: mean NLL over 6400 rows of 8000 logits --------------
__global__ void k_loss(const int* __restrict__ x, float* out) {
    int r = blockIdx.x;            // r = t*64 + b
    int t = r >> 6, b = r & 63;
    const float* row = &g_logits[(size_t)r * VV];
    int tid = threadIdx.x;
    float m = -INFINITY, s = 0.f;
    for (int v = tid; v < VV; v += 256) {
        float xv = row[v];
        if (xv > m) { s = s * expf(m - xv) + 1.f; m = xv; }
        else s += expf(xv - m);
    }
    __shared__ float sm[256], ss[256];
    sm[tid] = m; ss[tid] = s;
    __syncthreads();
    for (int o = 128; o; o >>= 1) {
        if (tid < o) {
            float m2 = sm[tid + o], s2 = ss[tid + o];
            float mm = fmaxf(sm[tid], m2);
            ss[tid] = ss[tid] * expf(sm[tid] - mm) + s2 * expf(m2 - mm);
            sm[tid] = mm;
        }
        __syncthreads();
    }
    if (tid == 0) {
        int tgt = x[b*TT + t + 1];
        float lse = sm[0] + logf(ss[0]);
        atomicAdd(out, (lse - row[tgt]) * (1.f / MM));
    }
}

// ---------------- transpose [t*64+b][v] -> out[b][v][t] ---------------------
__global__ void k_transpose(float* __restrict__ outLogits) {
    int b = blockIdx.x;
    int v0 = blockIdx.y * 32;
    __shared__ float tile[32 * 101];
    int tid = threadIdx.x;
    for (int idx = tid; idx < 3200; idx += 256) {
        int t = idx >> 5, vi = idx & 31;
        tile[vi*101 + t] = g_logits[(size_t)(t*BB + b)*VV + v0 + vi];
    }
    __syncthreads();
    for (int idx = tid; idx < 3200; idx += 256) {
        int vi = idx / 100, t = idx - vi*100;
        outLogits[(size_t)b*VV*TS + (size_t)(v0 + vi)*TS + t] = tile[vi*101 + t];
    }
}

// ---------------- launch ------------------------------------------------------
extern "C" void kernel_launch(void* const* d_in, const int* in_sizes, int n_in,
                              void* d_out, int out_size) {
    const int*   x   = (const int*)d_in[0];
    const float* emb = (const float*)d_in[1];
    const float* Wd  = (const float*)d_in[2];
    const float* bd  = (const float*)d_in[3];
    const float* Wih[3] = {(const float*)d_in[4],  (const float*)d_in[10], (const float*)d_in[16]};
    const float* Whh[3] = {(const float*)d_in[5],  (const float*)d_in[11], (const float*)d_in[17]};
    const float* bl[3]  = {(const float*)d_in[6],  (const float*)d_in[12], (const float*)d_in[18]};
    const float* gm[3]  = {(const float*)d_in[7],  (const float*)d_in[13], (const float*)d_in[19]};
    const float* bt[3]  = {(const float*)d_in[8],  (const float*)d_in[14], (const float*)d_in[20]};
    const float* mk[3]  = {(const float*)d_in[9],  (const float*)d_in[15], (const float*)d_in[21]};

    float* out = (float*)d_out;
    int hasLoss = (out_size & 1) ? 1 : 0;   // 51,200,001 odd => loss + logits
    float* outLogits = out + hasLoss;

    k_init<<<(3*HH*BB + 255)/256, 256>>>(out, hasLoss);
    k_embed<<<(MM*(HH/4) + 255)/256, 256>>>(x, emb);
    k_gemm_big<0><<<dim3(GG/128, MM/128), 256>>>(Wih[0], bl[0]);

    // wavefront over diagonals d = t + l, d in [0, TS+2)
    for (int d = 0; d < TS + 2; d++) {
        k_gemm_wave<<<dim3(32, 16, 3), 256>>>(d, Whh[0], Wih[1], Whh[1], Wih[2], Whh[2]);
        k_cell_wave<<<dim3(512, 3), 64>>>(d, bl[1], bl[2],
                                          gm[0], bt[0], mk[0],
                                          gm[1], bt[1], mk[1],
                                          gm[2], bt[2], mk[2]);
    }

    k_gemm_big<1><<<dim3((VV + 127)/128, MM/128), 256>>>(Wd, bd);
    if (hasLoss) k_loss<<<MM, 256>>>(x, out);
    k_transpose<<<dim3(BB, VV/32), 256>>>(outLogits);
}